// round 13
// baseline (speedup 1.0000x reference)
#include <cuda_runtime.h>
#include <math.h>

#define NN 100000
#define NE 1600000

// ---------------- static scratch (no allocations allowed) ----------------
__device__ int   g_row[NE];
__device__ int   g_col[NE];
__device__ int   g_cnt[NN];
__device__ int   g_ptr[NN + 1];
__device__ int   g_fill[NN];
__device__ int   g_src[NE];
__device__ int   g_is64;
__device__ __align__(16) float g_enorm[NE];
__device__ __align__(16) float g_dis[NN];
__device__ __align__(16) float g_z[(size_t)NN * 512];    // stacked z_k, row stride up to 512
__device__ __align__(16) float g_sa[(size_t)NN * 128];
__device__ __align__(16) float g_sb[(size_t)NN * 128];

// internal buffer IDs: 0=g_z 1=g_sa 2=g_sb
__device__ __forceinline__ float* devbuf(int id) {
    switch (id) {
        case 0: return g_z;
        case 1: return g_sa;
        default: return g_sb;
    }
}

// ---------------- JAX threefry2x32 (partitionable convention, CONFIRMED) ------------
__host__ __device__ __forceinline__ unsigned rotl32(unsigned x, int r) {
    return (x << r) | (x >> (32 - r));
}

__host__ __device__ inline void threefry2x32(unsigned k0, unsigned k1,
                                             unsigned x0, unsigned x1,
                                             unsigned& o0, unsigned& o1) {
    unsigned ks0 = k0, ks1 = k1, ks2 = k0 ^ k1 ^ 0x1BD11BDAu;
    x0 += ks0; x1 += ks1;
#define TF_R(r) { x0 += x1; x1 = rotl32(x1, (r)); x1 ^= x0; }
    TF_R(13) TF_R(15) TF_R(26) TF_R(6)   x0 += ks1; x1 += ks2 + 1u;
    TF_R(17) TF_R(29) TF_R(16) TF_R(24)  x0 += ks2; x1 += ks0 + 2u;
    TF_R(13) TF_R(15) TF_R(26) TF_R(6)   x0 += ks0; x1 += ks1 + 3u;
    TF_R(17) TF_R(29) TF_R(16) TF_R(24)  x0 += ks1; x1 += ks2 + 4u;
    TF_R(13) TF_R(15) TF_R(26) TF_R(6)   x0 += ks2; x1 += ks0 + 5u;
#undef TF_R
    o0 = x0; o1 = x1;
}

__device__ __forceinline__ float drop_apply(float v, int i, unsigned k0, unsigned k1) {
    unsigned o0, o1;
    threefry2x32(k0, k1, 0u, (unsigned)i, o0, o1);
    unsigned bits = o0 ^ o1;
    return (bits & 0x80000000u) ? 0.f : 2.0f * v;
}

// ---------------- f32x2 helpers ----------------
__device__ __forceinline__ unsigned long long dup2(float b) {
    unsigned long long r;
    asm("mov.b64 %0, {%1, %1};" : "=l"(r) : "f"(b));
    return r;
}
__device__ __forceinline__ void fma2(unsigned long long& acc, unsigned long long a,
                                     unsigned long long b) {
    asm("fma.rn.f32x2 %0, %1, %2, %0;" : "+l"(acc) : "l"(a), "l"(b));
}
__device__ __forceinline__ void unpack2(unsigned long long v, float& lo, float& hi) {
    asm("mov.b64 {%0, %1}, %2;" : "=f"(lo), "=f"(hi) : "l"(v));
}

// ---------------- graph prep ----------------
__global__ void zero_cnt_kernel() {
    int i = blockIdx.x * blockDim.x + threadIdx.x;
    if (i < NN) g_cnt[i] = 0;
}

__global__ void detect_kernel(const int* ei32) {
    if (blockIdx.x == 0 && threadIdx.x == 0) {
        int zeros = 0;
        for (int i = 1; i < 64; i += 2) zeros += (ei32[i] == 0);
        g_is64 = (zeros == 32) ? 1 : 0;
    }
}

__global__ void prep_edges(const void* eiv) {
    int e = blockIdx.x * blockDim.x + threadIdx.x;
    if (e >= NE) return;
    int r, c;
    if (g_is64) {
        const long long* ei = (const long long*)eiv;
        r = (int)ei[e];
        c = (int)ei[NE + e];
    } else {
        const int* ei = (const int*)eiv;
        r = ei[e];
        c = ei[NE + e];
    }
    if ((unsigned)r < NN && (unsigned)c < NN) {
        g_row[e] = r;
        g_col[e] = c;
        atomicAdd(&g_cnt[c], 1);
    } else {
        g_row[e] = -1;
        g_col[e] = 0;
    }
}

// single-block parallel scan (shared memory)
__global__ void scan_kernel() {
    const int T = 1024;
    __shared__ int ss[T];
    int t = threadIdx.x;
    const int chunk = (NN + T - 1) / T;    // 98
    int beg = t * chunk;
    int end = min(beg + chunk, NN);
    int s = 0;
    for (int i = beg; i < end; i++) s += g_cnt[i];
    ss[t] = s;
    __syncthreads();
    for (int off = 1; off < T; off <<= 1) {
        int v = (t >= off) ? ss[t - off] : 0;
        __syncthreads();
        ss[t] += v;
        __syncthreads();
    }
    int run = (t == 0) ? 0 : ss[t - 1];
    for (int i = beg; i < end; i++) { g_ptr[i] = run; run += g_cnt[i]; }
    if (t == T - 1) g_ptr[NN] = ss[T - 1];
}

__global__ void dis_fill_kernel() {
    int i = blockIdx.x * blockDim.x + threadIdx.x;
    if (i >= NN) return;
    int c = g_cnt[i];
    g_dis[i] = (c > 0) ? (1.0f / sqrtf((float)c)) : 0.0f;
    g_fill[i] = g_ptr[i];
}

__global__ void fill_csr_kernel() {
    int e = blockIdx.x * blockDim.x + threadIdx.x;
    if (e >= NE) return;
    int r = g_row[e];
    if (r < 0) return;
    int c = g_col[e];
    int p = atomicAdd(&g_fill[c], 1);
    g_src[p] = r;
    g_enorm[p] = g_dis[r] * g_dis[c];
}

// ---------------- GEMM: z[n, 0:ntot] = X[n, 0:KD] @ Wstk[ntot, KD]^T (+bias cols<blim)
// f32x2 inner loop: full-rate FFMA2. BM=128, BK=16, BN in {128, 64}.
template <int BN, int KD>
__global__ void gemm_f32x2(const float* X_ext, int X_id,
                           const float* __restrict__ W,
                           const float* __restrict__ bias, int blim,
                           int ntot, float* out_ext, int out_id) {
    constexpr int BM = 128;
    constexpr int BK = 16;
    constexpr int TP = (BN == 128) ? 4 : 2;     // M-pairs per thread (rows = 2*TP)
    constexpr int TDIV = 2048 / BN;             // 16 (BN=128) or 32 (BN=64)

    __shared__ __align__(16) float As[BK][BM];
    __shared__ __align__(16) float Bs[BK][BN];

    const float* X = X_ext ? X_ext : devbuf(X_id);
    float* out = out_ext ? out_ext : devbuf(out_id);

    const int tid = threadIdx.x;                // 256 threads
    const int m0 = (tid % TDIV) * (2 * TP);
    const int n0 = (tid / TDIV) * 8;
    const int mb = blockIdx.x * BM;
    const int cb = blockIdx.y * BN;

    unsigned long long acc[TP][8];
#pragma unroll
    for (int i = 0; i < TP; i++)
#pragma unroll
        for (int j = 0; j < 8; j++) acc[i][j] = 0ull;

    for (int kc = 0; kc < KD; kc += BK) {
        // As[d][m] = X[mb+m][kc+d]   (128x16 floats, transposed load)
#pragma unroll
        for (int it = 0; it < 2; it++) {
            int idx = tid + it * 256;           // 0..511
            int dq = idx & 3, nl = idx >> 2;    // nl 0..127
            int node = mb + nl;
            float4 v = make_float4(0.f, 0.f, 0.f, 0.f);
            if (node < NN) v = *reinterpret_cast<const float4*>(&X[(size_t)node * KD + kc + dq * 4]);
            As[dq * 4 + 0][nl] = v.x;
            As[dq * 4 + 1][nl] = v.y;
            As[dq * 4 + 2][nl] = v.z;
            As[dq * 4 + 3][nl] = v.w;
        }
        // Bs[d][o] = W[cb+o][kc+d]
#pragma unroll
        for (int it = 0; it < BN / 64; it++) {
            int idx = tid + it * 256;
            int dq = idx & 3, ol = idx >> 2;    // ol 0..BN-1
            int orow = cb + ol;
            float4 v = *reinterpret_cast<const float4*>(&W[(size_t)orow * KD + kc + dq * 4]);
            Bs[dq * 4 + 0][ol] = v.x;
            Bs[dq * 4 + 1][ol] = v.y;
            Bs[dq * 4 + 2][ol] = v.z;
            Bs[dq * 4 + 3][ol] = v.w;
        }
        __syncthreads();

#pragma unroll
        for (int d = 0; d < BK; d++) {
            unsigned long long ap[TP];
            {
                ulonglong2 a01 = *reinterpret_cast<const ulonglong2*>(&As[d][m0]);
                ap[0] = a01.x; ap[1] = a01.y;
                if (TP == 4) {
                    ulonglong2 a23 = *reinterpret_cast<const ulonglong2*>(&As[d][m0 + 4]);
                    ap[2] = a23.x; ap[3] = a23.y;
                }
            }
            float4 b0 = *reinterpret_cast<const float4*>(&Bs[d][n0]);
            float4 b1 = *reinterpret_cast<const float4*>(&Bs[d][n0 + 4]);
            unsigned long long bd[8];
            bd[0] = dup2(b0.x); bd[1] = dup2(b0.y); bd[2] = dup2(b0.z); bd[3] = dup2(b0.w);
            bd[4] = dup2(b1.x); bd[5] = dup2(b1.y); bd[6] = dup2(b1.z); bd[7] = dup2(b1.w);
#pragma unroll
            for (int i = 0; i < TP; i++)
#pragma unroll
                for (int j = 0; j < 8; j++) fma2(acc[i][j], ap[i], bd[j]);
        }
        __syncthreads();
    }

    // bias values for this thread's 8 columns
    float bvals[8];
#pragma unroll
    for (int j = 0; j < 8; j++) {
        int gcol = cb + n0 + j;
        bvals[j] = (bias && gcol < blim) ? bias[gcol] : 0.f;
    }

#pragma unroll
    for (int i = 0; i < TP; i++) {
        float lo[8], hi[8];
#pragma unroll
        for (int j = 0; j < 8; j++) unpack2(acc[i][j], lo[j], hi[j]);
        int row0 = mb + m0 + 2 * i;
        if (row0 < NN) {
            float* po = out + (size_t)row0 * ntot + cb + n0;
            float4 s0 = make_float4(lo[0] + bvals[0], lo[1] + bvals[1], lo[2] + bvals[2], lo[3] + bvals[3]);
            float4 s1 = make_float4(lo[4] + bvals[4], lo[5] + bvals[5], lo[6] + bvals[6], lo[7] + bvals[7]);
            *reinterpret_cast<float4*>(po) = s0;
            *reinterpret_cast<float4*>(po + 4) = s1;
        }
        if (row0 + 1 < NN) {
            float* po = out + (size_t)(row0 + 1) * ntot + cb + n0;
            float4 s0 = make_float4(hi[0] + bvals[0], hi[1] + bvals[1], hi[2] + bvals[2], hi[3] + bvals[3]);
            float4 s1 = make_float4(hi[4] + bvals[4], hi[5] + bvals[5], hi[6] + bvals[6], hi[7] + bvals[7]);
            *reinterpret_cast<float4*>(po) = s0;
            *reinterpret_cast<float4*>(po + 4) = s1;
        }
    }
}

// ---------------- fused Horner hop: out[c] = sum_e norm*hin[src] + z[c] (+post) ------
// POST: 0 = none, 1 = dropout, 2 = elu+dropout
template <int D, int POST>
__global__ void prop_fused(const float* hin_ext, int hin_id, int hin_str, int hin_off,
                           int z_str, int z_off,
                           float* out_ext, int out_id,
                           unsigned k0, unsigned k1) {
    const float* __restrict__ hin = (hin_ext ? hin_ext : devbuf(hin_id)) + hin_off;
    const float* __restrict__ z = g_z + z_off;
    float* __restrict__ outp = out_ext ? out_ext : devbuf(out_id);
    int w = blockIdx.x * (blockDim.x >> 5) + (threadIdx.x >> 5);
    if (w >= NN) return;
    int lane = threadIdx.x & 31;
    int s = g_ptr[w], e = g_ptr[w + 1];

    if (D == 128) {
        float4 acc = make_float4(0.f, 0.f, 0.f, 0.f);
        for (int i = s; i < e; i++) {
            int r = g_src[i];
            float wt = g_enorm[i];
            float4 v = *reinterpret_cast<const float4*>(hin + (size_t)r * hin_str + lane * 4);
            acc.x += wt * v.x; acc.y += wt * v.y; acc.z += wt * v.z; acc.w += wt * v.w;
        }
        float4 zv = *reinterpret_cast<const float4*>(z + (size_t)w * z_str + lane * 4);
        acc.x += zv.x; acc.y += zv.y; acc.z += zv.z; acc.w += zv.w;
        if (POST == 1) {
            int i0 = w * 128 + lane * 4;
            acc.x = drop_apply(acc.x, i0 + 0, k0, k1);
            acc.y = drop_apply(acc.y, i0 + 1, k0, k1);
            acc.z = drop_apply(acc.z, i0 + 2, k0, k1);
            acc.w = drop_apply(acc.w, i0 + 3, k0, k1);
        }
        *reinterpret_cast<float4*>(outp + (size_t)w * 128 + lane * 4) = acc;
    } else if (D == 64) {
        float2 acc = make_float2(0.f, 0.f);
        for (int i = s; i < e; i++) {
            int r = g_src[i];
            float wt = g_enorm[i];
            float2 v = *reinterpret_cast<const float2*>(hin + (size_t)r * hin_str + lane * 2);
            acc.x += wt * v.x; acc.y += wt * v.y;
        }
        float2 zv = *reinterpret_cast<const float2*>(z + (size_t)w * z_str + lane * 2);
        acc.x += zv.x; acc.y += zv.y;
        if (POST == 2) {
            acc.x = (acc.x > 0.f) ? acc.x : expm1f(acc.x);
            acc.y = (acc.y > 0.f) ? acc.y : expm1f(acc.y);
            int i0 = w * 64 + lane * 2;
            acc.x = drop_apply(acc.x, i0 + 0, k0, k1);
            acc.y = drop_apply(acc.y, i0 + 1, k0, k1);
        }
        *reinterpret_cast<float2*>(outp + (size_t)w * 64 + lane * 2) = acc;
    } else {  // D == 16
        if (lane < 16) {
            float acc = 0.f;
            for (int i = s; i < e; i++) {
                int r = g_src[i];
                acc += g_enorm[i] * hin[(size_t)r * hin_str + lane];
            }
            acc += z[(size_t)w * z_str + lane];
            outp[(size_t)w * 16 + lane] = acc;
        }
    }
}

// ---------------- host orchestration: kernel launches ONLY ----------------
extern "C" void kernel_launch(void* const* d_in, const int* in_sizes, int n_in,
                              void* d_out, int out_size) {
    const float* x  = (const float*)d_in[0];
    const void*  ei = (const void*)d_in[1];
    const float* W1 = (const float*)d_in[2];
    const float* b1 = (const float*)d_in[3];
    const float* W2 = (const float*)d_in[4];
    const float* b2 = (const float*)d_in[5];
    const float* W3 = (const float*)d_in[6];
    const float* b3 = (const float*)d_in[7];
    float* out = (float*)d_out;

    // dropout keys: split(key(42)) partitionable = threefry((0,42),(0,j)) -- confirmed
    unsigned d10, d11, d20, d21;
    threefry2x32(0u, 42u, 0u, 0u, d10, d11);
    threefry2x32(0u, 42u, 0u, 1u, d20, d21);

    // graph prep
    zero_cnt_kernel<<<(NN + 255) / 256, 256>>>();
    detect_kernel<<<1, 32>>>((const int*)ei);
    prep_edges<<<(NE + 255) / 256, 256>>>(ei);
    scan_kernel<<<1, 1024>>>();
    dis_fill_kernel<<<(NN + 255) / 256, 256>>>();
    fill_csr_kernel<<<(NE + 255) / 256, 256>>>();

    const int mgrid = (NN + 127) / 128;    // 782
    const int pgrid = (NN + 7) / 8;        // 8 warps / 256-thread block

    // ---- layer 1: z = x @ W1stk^T [100k,512]; Horner props at 128d ----
    gemm_f32x2<128, 128><<<dim3(mgrid, 4), 256>>>(x, -1, W1, b1, 128, 512, nullptr, 0);
    prop_fused<128, 0><<<pgrid, 256>>>(nullptr, 0, 512, 3 * 128, 512, 2 * 128, nullptr, 1, 0u, 0u); // sa = A z3 + z2
    prop_fused<128, 0><<<pgrid, 256>>>(nullptr, 1, 128, 0, 512, 128, nullptr, 2, 0u, 0u);           // sb = A sa + z1
    prop_fused<128, 1><<<pgrid, 256>>>(nullptr, 2, 128, 0, 512, 0, nullptr, 1, d10, d11);           // sa = drop(A sb + z0)

    // ---- layer 2: z = h1 @ W2stk^T [100k,256]; props at 64d ----
    gemm_f32x2<128, 128><<<dim3(mgrid, 2), 256>>>(nullptr, 1, W2, b2, 64, 256, nullptr, 0);
    prop_fused<64, 0><<<pgrid, 256>>>(nullptr, 0, 256, 3 * 64, 256, 2 * 64, nullptr, 2, 0u, 0u);    // sb = A z3 + z2
    prop_fused<64, 0><<<pgrid, 256>>>(nullptr, 2, 64, 0, 256, 64, nullptr, 1, 0u, 0u);              // sa = A sb + z1
    prop_fused<64, 2><<<pgrid, 256>>>(nullptr, 1, 64, 0, 256, 0, nullptr, 2, d20, d21);             // sb = drop(elu(A sa + z0))

    // ---- layer 3: z = h2 @ W3stk^T [100k,64]; props at 16d ----
    gemm_f32x2<64, 64><<<dim3(mgrid, 1), 256>>>(nullptr, 2, W3, b3, 16, 64, nullptr, 0);
    prop_fused<16, 0><<<pgrid, 256>>>(nullptr, 0, 64, 3 * 16, 64, 2 * 16, nullptr, 1, 0u, 0u);      // sa = A z3 + z2
    prop_fused<16, 0><<<pgrid, 256>>>(nullptr, 1, 16, 0, 64, 16, nullptr, 2, 0u, 0u);               // sb = A sa + z1
    prop_fused<16, 0><<<pgrid, 256>>>(nullptr, 2, 16, 0, 64, 0, out, -1, 0u, 0u);                   // out = A sb + z0
}